// round 4
// baseline (speedup 1.0000x reference)
#include <cuda_runtime.h>
#include <cuda_pipeline.h>
#include <math.h>

// Problem shape (fixed by setup_inputs)
#define NN 512
#define EE 64
#define OO 64
#define KK 8
#define NT 512
#define CHN 16              // n-rows per chunk
#define NCH (NN / CHN)      // 32 chunks per iteration
#define NPAD 68             // padded priors row stride (floats)

// ---- shared memory layout (byte offsets) ----
#define OFF_STAGE   0                    // 2 x 32768 B staging ring
#define STAGE_FLTS  8192                 // floats per stage (8k*16n*64o)
#define OFF_PRIORS  65536                // [512][68] fp32 = 139264 B
#define OFF_DELTA   204800               // [8][512]  fp32 =  16384 B
#define OFF_Z       221184               // [8][64]   fp32 =   2048 B
#define OFF_V       223232               // [8][64]   fp32 =   2048 B
#define SMEM_TOTAL  225280
// aliases (stage area is idle when these are used)
#define OFF_SMAT    0                    // phase A only: [64][64] fp32 = 16 KB
#define OFF_ZRED    0                    // post-drain:  [16][8][64] fp32 = 32 KB

__global__ void __launch_bounds__(NT, 1)
routing_kernel(const float* __restrict__ emb,
               const float* __restrict__ S,
               const float* __restrict__ cc0,
               float* __restrict__ out)
{
    extern __shared__ __align__(16) char smraw[];
    float* stage = reinterpret_cast<float*>(smraw + OFF_STAGE);
    float (*priors)[NPAD] = reinterpret_cast<float(*)[NPAD]>(smraw + OFF_PRIORS);
    float (*delta)[NN]    = reinterpret_cast<float(*)[NN]>(smraw + OFF_DELTA);
    float (*zsh)[OO]      = reinterpret_cast<float(*)[OO]>(smraw + OFF_Z);
    float (*vsh)[OO]      = reinterpret_cast<float(*)[OO]>(smraw + OFF_V);
    float (*Smat)[OO]     = reinterpret_cast<float(*)[OO]>(smraw + OFF_SMAT);
    float* zred           = reinterpret_cast<float*>(smraw + OFF_ZRED);

    const int b    = blockIdx.x;
    const int t    = threadIdx.x;
    const int lane = t & 31;
    const int warp = t >> 5;
    // streaming decomposition: warp <-> n-row within chunk; lane = (kh, o4)
    const int o4 = t & 15;          // which float4 of the O=64 row
    const int kh = (t >> 4) & 1;    // k half: k = kh*4 + j
    const int nl = t >> 5;          // n within chunk (== warp)

    // ---- load S into (aliased) smem + zero delta ----
    {
        const float4* src = reinterpret_cast<const float4*>(S);
        float4* dst = reinterpret_cast<float4*>(&Smat[0][0]);
        for (int i = t; i < (EE * OO) / 4; i += NT) dst[i] = src[i];
    }
    for (int i = t; i < KK * NN; i += NT) (&delta[0][0])[i] = 0.0f;
    __syncthreads();

    // ---- Phase A: priors[n][o] = sum_e emb[b,n,e] * S[e,o] ----
    {
        const int o4A = t & 15;
        const int ngA = t >> 4;           // 32 n-groups
        const float* embb = emb + (size_t)b * NN * EE;
        #pragma unroll 1
        for (int i = 0; i < 16; i++) {
            const int n = ngA + 32 * i;
            const float4* erow = reinterpret_cast<const float4*>(embb + n * EE);
            float4 acc = make_float4(0.f, 0.f, 0.f, 0.f);
            #pragma unroll
            for (int e4 = 0; e4 < EE / 4; e4++) {
                float4 a  = erow[e4];
                float4 s0 = *reinterpret_cast<const float4*>(&Smat[4*e4+0][o4A*4]);
                float4 s1 = *reinterpret_cast<const float4*>(&Smat[4*e4+1][o4A*4]);
                float4 s2 = *reinterpret_cast<const float4*>(&Smat[4*e4+2][o4A*4]);
                float4 s3 = *reinterpret_cast<const float4*>(&Smat[4*e4+3][o4A*4]);
                acc.x += a.x*s0.x + a.y*s1.x + a.z*s2.x + a.w*s3.x;
                acc.y += a.x*s0.y + a.y*s1.y + a.z*s2.y + a.w*s3.y;
                acc.z += a.x*s0.z + a.y*s1.z + a.z*s2.z + a.w*s3.z;
                acc.w += a.x*s0.w + a.y*s1.w + a.z*s2.w + a.w*s3.w;
            }
            *reinterpret_cast<float4*>(&priors[n][o4A * 4]) = acc;
        }
    }
    __syncthreads();   // Smat alias (stage area) free after this

    const float* ccb = cc0 + (size_t)b * KK * NN * OO;

    // per-thread global src base for its 4 async copies (k = kh*4+j), chunk 0
    // src(k, n, o) = ccb + (k*NN + n)*OO + o
    const float* src_base = ccb + ((size_t)(kh * 4) * NN + nl) * OO + o4 * 4;
    // smem dst base (floats) for its 4 stores in a stage
    const int dst_flt = (((kh * 4) * CHN + nl) * OO + o4 * 4);

    #pragma unroll 1
    for (int it = 0; it < 3; it++) {
        // ---- pipeline prologue: chunks 0 and 1 ----
        #pragma unroll
        for (int s = 0; s < 2; s++) {
            const float* src = src_base + (size_t)s * CHN * OO;
            float* dst = stage + s * STAGE_FLTS + dst_flt;
            #pragma unroll
            for (int j = 0; j < 4; j++)
                __pipeline_memcpy_async(dst + j * (CHN * OO),
                                        src + (size_t)j * NN * OO, 16);
            __pipeline_commit();
        }

        float4 zp[4];
        #pragma unroll
        for (int j = 0; j < 4; j++) zp[j] = make_float4(0.f, 0.f, 0.f, 0.f);

        #pragma unroll 1
        for (int ch = 0; ch < NCH; ch++) {
            if (ch < NCH - 1) __pipeline_wait_prior(1);
            else              __pipeline_wait_prior(0);
            __syncthreads();

            const int n = ch * CHN + nl;
            const float* stg = stage + (ch & 1) * STAGE_FLTS;

            // delta for my 4 k's; max over all 8 via partner shuffle
            float d[4];
            float dm = -1e30f;
            #pragma unroll
            for (int j = 0; j < 4; j++) { d[j] = delta[kh * 4 + j][n]; dm = fmaxf(dm, d[j]); }
            dm = fmaxf(dm, __shfl_xor_sync(0xffffffffu, dm, 16));

            float4 p = *reinterpret_cast<const float4*>(&priors[n][o4 * 4]);

            float4 e[4];
            float sx = 0.f, sy = 0.f, sz = 0.f, sw = 0.f;
            #pragma unroll
            for (int j = 0; j < 4; j++) {
                float4 c = *reinterpret_cast<const float4*>(
                    &stg[((kh * 4 + j) * CHN + nl) * OO + o4 * 4]);
                const float dk = d[j] - dm;
                e[j].x = __expf(c.x + dk); sx += e[j].x;
                e[j].y = __expf(c.y + dk); sy += e[j].y;
                e[j].z = __expf(c.z + dk); sz += e[j].z;
                e[j].w = __expf(c.w + dk); sw += e[j].w;
            }
            // complete the k-sum with the partner half-warp
            sx += __shfl_xor_sync(0xffffffffu, sx, 16);
            sy += __shfl_xor_sync(0xffffffffu, sy, 16);
            sz += __shfl_xor_sync(0xffffffffu, sz, 16);
            sw += __shfl_xor_sync(0xffffffffu, sw, 16);

            const float gx = __fdividef(p.x, sx);
            const float gy = __fdividef(p.y, sy);
            const float gz = __fdividef(p.z, sz);
            const float gw = __fdividef(p.w, sw);
            #pragma unroll
            for (int j = 0; j < 4; j++) {
                zp[j].x += e[j].x * gx;
                zp[j].y += e[j].y * gy;
                zp[j].z += e[j].z * gz;
                zp[j].w += e[j].w * gw;
            }

            __syncthreads();   // stage slot free for refill
            if (ch + 2 < NCH) {
                const float* src = src_base + (size_t)(ch + 2) * CHN * OO;
                float* dst = stage + (ch & 1) * STAGE_FLTS + dst_flt;
                #pragma unroll
                for (int j = 0; j < 4; j++)
                    __pipeline_memcpy_async(dst + j * (CHN * OO),
                                            src + (size_t)j * NN * OO, 16);
                __pipeline_commit();
            }
        }

        // ---- reduce z over the 16 warps (zred aliases drained stage[0]) ----
        #pragma unroll
        for (int j = 0; j < 4; j++)
            *reinterpret_cast<float4*>(&zred[((nl * KK) + kh * 4 + j) * OO + o4 * 4]) = zp[j];
        __syncthreads();
        {
            const int k = t >> 6, o = t & 63;   // 512 threads == K*O outputs
            float s = 0.f;
            #pragma unroll
            for (int w = 0; w < 16; w++) s += zred[((w * KK) + k) * OO + o];
            zsh[k][o] = s;
        }
        __syncthreads();

        // ---- squash: warp w handles capsule k = w ----
        if (warp < KK) {
            const int k = warp;
            const float z0 = zsh[k][lane];
            const float z1 = zsh[k][lane + 32];
            float sq = z0 * z0 + z1 * z1;
            #pragma unroll
            for (int s2 = 16; s2 > 0; s2 >>= 1) sq += __shfl_xor_sync(0xffffffffu, sq, s2);
            const float f = sq / ((1.0f + sq) * sqrtf(sq + 1e-9f));
            if (it == 2) {
                float* ob = out + (size_t)b * KK * OO + (size_t)k * OO;
                ob[lane]      = f * z0;
                ob[lane + 32] = f * z1;
            } else {
                vsh[k][lane]      = f * z0;
                vsh[k][lane + 32] = f * z1;
            }
        }
        if (it == 2) break;
        __syncthreads();

        // ---- sim pass: delta[k][n] += <priors[n,:], v[k,:]>; thread t <-> n ----
        {
            const int n = t;
            float sim[KK];
            #pragma unroll
            for (int k = 0; k < KK; k++) sim[k] = 0.f;
            #pragma unroll
            for (int oo = 0; oo < 16; oo++) {
                float4 pp = *reinterpret_cast<const float4*>(&priors[n][oo * 4]);
                #pragma unroll
                for (int k = 0; k < KK; k++) {
                    float4 vv = *reinterpret_cast<const float4*>(&vsh[k][oo * 4]);
                    sim[k] += pp.x * vv.x + pp.y * vv.y + pp.z * vv.z + pp.w * vv.w;
                }
            }
            #pragma unroll
            for (int k = 0; k < KK; k++) delta[k][n] += sim[k];
        }
        __syncthreads();   // delta ready; stage area free for next iter prologue
    }
}

extern "C" void kernel_launch(void* const* d_in, const int* in_sizes, int n_in,
                              void* d_out, int out_size)
{
    const float* emb = (const float*)d_in[0];   // (B, N, E) fp32
    const float* S   = (const float*)d_in[1];   // (E, O)   fp32
    const float* cc  = (const float*)d_in[2];   // (B, K, N, O) fp32
    float* out       = (float*)d_out;           // (B, K, O) fp32

    const int Bv = in_sizes[0] / (NN * EE);     // 256

    cudaFuncSetAttribute(routing_kernel,
                         cudaFuncAttributeMaxDynamicSharedMemorySize, SMEM_TOTAL);

    routing_kernel<<<Bv, NT, SMEM_TOTAL>>>(emb, S, cc, out);
}